// round 14
// baseline (speedup 1.0000x reference)
#include <cuda_runtime.h>
#include <cuda_bf16.h>
#include <cstdint>

// Problem constants
#define T_ 64
#define B_ 16
#define DIM_ 512
#define H_ 8
#define DH_ 64
#define ETA_ 4
#define FD_ 256           // ETA_*DH_
#define NPROJ 2656        // 5*512 + 3*32
#define NPROJ_PAD 2688
#define MROWS 1024        // T_*B_

// Output layout: output[T,B,DIM], kv_last[B,H,FD,Dh], nm_last[B,H,FD]
#define OUT_OFF_KV  (T_*B_*DIM_)
#define OUT_OFF_NM  (OUT_OFF_KV + B_*H_*FD_*DH_)

// Scratch (device globals — no allocation allowed)
__device__ float g_proj[MROWS * NPROJ_PAD];
__device__ float g_attn[MROWS * (H_*DH_)];

// ---------------------------------------------------------------------------
// f32x2 packed helpers
// ---------------------------------------------------------------------------
__device__ __forceinline__ unsigned long long pk2(float lo, float hi) {
    unsigned long long r;
    asm("mov.b64 %0, {%1, %2};" : "=l"(r) : "f"(lo), "f"(hi));
    return r;
}
__device__ __forceinline__ void unpk2(float& lo, float& hi, unsigned long long v) {
    asm("mov.b64 {%0, %1}, %2;" : "=f"(lo), "=f"(hi) : "l"(v));
}
__device__ __forceinline__ unsigned long long fma2_(unsigned long long a,
                                                    unsigned long long b,
                                                    unsigned long long c) {
    unsigned long long d;
    asm("fma.rn.f32x2 %0, %1, %2, %3;" : "=l"(d) : "l"(a), "l"(b), "l"(c));
    return d;
}
__device__ __forceinline__ unsigned long long mul2_(unsigned long long a,
                                                    unsigned long long b) {
    unsigned long long d;
    asm("mul.rn.f32x2 %0, %1, %2;" : "=l"(d) : "l"(a), "l"(b));
    return d;
}

__device__ __forceinline__ float sigmoidf_(float x) {
    return 1.f / (1.f + __expf(-x));
}

// ---------------------------------------------------------------------------
// GEMM 1: projections (measured R3/R9 config: 64x64x16, 4x4 micro, 256 thr)
// ---------------------------------------------------------------------------
#define BM 64
#define BN 64
#define BK 16

__global__ __launch_bounds__(256)
void proj_gemm(const float* __restrict__ X,
               const float* __restrict__ Wq, const float* __restrict__ Wk,
               const float* __restrict__ Wv, const float* __restrict__ Wb,
               const float* __restrict__ Wg, const float* __restrict__ Wp1,
               const float* __restrict__ Wp2, const float* __restrict__ Wp3)
{
    __shared__ float Xs[BK][BM + 4];
    __shared__ float Ws[BK][BN + 4];

    const int tid = threadIdx.x;
    const int m0 = blockIdx.y * BM;
    const int n0 = blockIdx.x * BN;

    const int lr = tid >> 2;
    const int lc = (tid & 3) * 4;
    const int tx = tid & 15;
    const int ty = tid >> 4;

    const int n = n0 + lr;
    const float* wrow = nullptr;
    if (n < 2560) {
        const int wi = n >> 9;
        const int nl = n & 511;
        const float* wb = (wi == 0) ? Wq : (wi == 1) ? Wk : (wi == 2) ? Wv
                         : (wi == 3) ? Wb : Wg;
        wrow = wb + nl * DIM_;
    } else if (n < NPROJ) {
        const int nn = n - 2560;
        const int wi = nn >> 5;
        const int nl = nn & 31;
        const float* wb = (wi == 0) ? Wp1 : (wi == 1) ? Wp2 : Wp3;
        wrow = wb + nl * DIM_;
    }
    const float* xrow = X + (size_t)(m0 + lr) * DIM_;

    float acc[4][4];
#pragma unroll
    for (int i = 0; i < 4; i++)
#pragma unroll
        for (int j = 0; j < 4; j++) acc[i][j] = 0.f;

    for (int k0 = 0; k0 < DIM_; k0 += BK) {
        float4 xv = *(const float4*)(xrow + k0 + lc);
        float4 wv = make_float4(0.f, 0.f, 0.f, 0.f);
        if (wrow) wv = *(const float4*)(wrow + k0 + lc);
        Xs[lc + 0][lr] = xv.x; Xs[lc + 1][lr] = xv.y;
        Xs[lc + 2][lr] = xv.z; Xs[lc + 3][lr] = xv.w;
        Ws[lc + 0][lr] = wv.x; Ws[lc + 1][lr] = wv.y;
        Ws[lc + 2][lr] = wv.z; Ws[lc + 3][lr] = wv.w;
        __syncthreads();
#pragma unroll
        for (int kk = 0; kk < BK; kk++) {
            float4 a = *(const float4*)&Xs[kk][ty * 4];
            float4 bq = *(const float4*)&Ws[kk][tx * 4];
            float av[4] = {a.x, a.y, a.z, a.w};
            float bv[4] = {bq.x, bq.y, bq.z, bq.w};
#pragma unroll
            for (int i = 0; i < 4; i++)
#pragma unroll
                for (int j = 0; j < 4; j++) acc[i][j] += av[i] * bv[j];
        }
        __syncthreads();
    }

#pragma unroll
    for (int i = 0; i < 4; i++) {
        const int m = m0 + ty * 4 + i;
#pragma unroll
        for (int j = 0; j < 4; j++) {
            g_proj[(size_t)m * NPROJ_PAD + n0 + tx * 4 + j] = acc[i][j];
        }
    }
}

// ---------------------------------------------------------------------------
// GEMM 2: direct output GEMM with fused bias (R9 measured).
// ---------------------------------------------------------------------------
__global__ __launch_bounds__(256)
void out_gemm(const float* __restrict__ Wo, const float* __restrict__ bo,
              float* __restrict__ out)
{
    __shared__ float Xs[BK][BM + 4];
    __shared__ float Ws[BK][BN + 4];

    const int tid = threadIdx.x;
    const int m0 = blockIdx.y * BM;
    const int n0 = blockIdx.x * BN;

    const int lr = tid >> 2;
    const int lc = (tid & 3) * 4;
    const int tx = tid & 15;
    const int ty = tid >> 4;

    const float* xrow = g_attn + (size_t)(m0 + lr) * DIM_;
    const float* wrow = Wo + (size_t)(n0 + lr) * DIM_;

    float acc[4][4];
#pragma unroll
    for (int i = 0; i < 4; i++)
#pragma unroll
        for (int j = 0; j < 4; j++) acc[i][j] = 0.f;

    for (int k0 = 0; k0 < DIM_; k0 += BK) {
        float4 xv = *(const float4*)(xrow + k0 + lc);
        float4 wv = *(const float4*)(wrow + k0 + lc);
        Xs[lc + 0][lr] = xv.x; Xs[lc + 1][lr] = xv.y;
        Xs[lc + 2][lr] = xv.z; Xs[lc + 3][lr] = xv.w;
        Ws[lc + 0][lr] = wv.x; Ws[lc + 1][lr] = wv.y;
        Ws[lc + 2][lr] = wv.z; Ws[lc + 3][lr] = wv.w;
        __syncthreads();
#pragma unroll
        for (int kk = 0; kk < BK; kk++) {
            float4 a = *(const float4*)&Xs[kk][ty * 4];
            float4 bq = *(const float4*)&Ws[kk][tx * 4];
            float av[4] = {a.x, a.y, a.z, a.w};
            float bv[4] = {bq.x, bq.y, bq.z, bq.w};
#pragma unroll
            for (int i = 0; i < 4; i++)
#pragma unroll
                for (int j = 0; j < 4; j++)
                    acc[i][j] = fmaf(av[i], bv[j], acc[i][j]);
        }
        __syncthreads();
    }

#pragma unroll
    for (int i = 0; i < 4; i++) {
        const int m = m0 + ty * 4 + i;
#pragma unroll
        for (int j = 0; j < 4; j++) {
            const int nn = n0 + tx * 4 + j;
            out[(size_t)m * DIM_ + nn] = acc[i][j] + bo[nn];
        }
    }
}

// ---------------------------------------------------------------------------
// Scan kernel v6: FOUR blocks per (b,h), split along Dh (d-quarters).
//   blockIdx.x = bh*4 + ds; block handles d in [ds*16, ds*16+16).
//   Thread map: fg = tid>>5 (FD group of 32 rows), jh = (tid>>4)&1
//   (16-row half of the group), dloc = tid&15.
//   Per-thread kv state: 16 floats = 8 packed f32x2.
//   num reduction: 1 shfl (xor 16, combines jh) + 8-way smem sum in phase C.
//   CHUNK-2 structure retained from the measured R9 kernel.
// ---------------------------------------------------------------------------
__global__ __launch_bounds__(256)
void scan_kernel(const int* __restrict__ term,
                 const float* __restrict__ kv_prev,
                 const float* __restrict__ nm_prev,
                 float* __restrict__ kv_out,
                 float* __restrict__ nm_out)
{
    const int blk = blockIdx.x;      // 0..511
    const int bh  = blk >> 2;        // 0..127
    const int ds  = blk & 3;         // d-quarter
    const int b   = bh >> 3;
    const int h   = bh & 7;
    const int tid = threadIdx.x;
    const int fg  = tid >> 5;        // 0..7 : FD group (32 rows)
    const int jh  = (tid >> 4) & 1;  // row half within group
    const int dloc = tid & 15;
    const int d   = ds * 16 + dloc;  // global head-dim column
    const int ED  = tid;             // FD index for phase A
    const int e   = ED >> 6;
    const int dd  = ED & 63;

    __shared__ float s_disc[2][FD_];
    __shared__ float s_gk[2][FD_];
    __shared__ float s_phi[2][FD_];
    __shared__ float s_gv[2][16];
    __shared__ float s_numred[2][8][17];  // [step][fg][dloc] (+pad)
    __shared__ float s_denred[2][2][8];   // [parity][step][fg]

    // kv state: rows [fg*32 + jh*16, +16) for column d, packed pairs
    unsigned long long kv2[8];
    {
        const float* kvp = kv_prev + (size_t)bh * FD_ * DH_;
        const int rbase = fg * 32 + jh * 16;
#pragma unroll
        for (int p = 0; p < 8; p++) {
            const float lo = kvp[(rbase + 2*p    ) * DH_ + d];
            const float hi = kvp[(rbase + 2*p + 1) * DH_ + d];
            kv2[p] = pk2(lo, hi);
        }
    }
    float nm = nm_prev[bh * FD_ + ED];

    const int hcol = h * DH_;
    const int pofs = h * ETA_ + e;

    float rq[2], rk[2], rg[2], rp1[2], rp2[2], rp3[2], rv[2], rb[2];
    int rtm[2];

    // prefetch chunk 0 (steps 0,1)
#pragma unroll
    for (int i = 0; i < 2; i++) {
        const float* P = g_proj + (size_t)(i * B_ + b) * NPROJ_PAD;
        rq[i]  = P[hcol + dd];
        rk[i]  = P[512 + hcol + dd];
        rg[i]  = P[2048 + hcol + dd];
        rp1[i] = P[2560 + pofs];
        rp2[i] = P[2592 + pofs];
        rp3[i] = P[2624 + pofs];
        rtm[i] = term[i * B_ + b];
        if (tid < 16) {
            rv[i] = P[1024 + hcol + ds * 16 + tid];
            rb[i] = P[1536 + hcol + ds * 16 + tid];
        }
    }

    for (int c = 0; c < 32; c++) {
        const int par = c & 1;

        // ---- phase A: 2 steps of per-FD quantities + nm chain ----
        float den[2];
#pragma unroll
        for (int i = 0; i < 2; i++) {
            const float sgamma = sigmoidf_(rg[i]);
            const float gf   = sigmoidf_(rp3[i]) * sgamma;
            const float mask = rtm[i] ? 0.f : 1.f;
            const float disc = (1.f - gf) * mask;
            const float gkv  = fmaxf(rp1[i], 0.f) * rk[i] * gf;
            const float phi  = fmaxf(rp2[i], 0.f) * rq[i];
            s_disc[i][ED] = disc;
            s_gk[i][ED]   = gkv;
            s_phi[i][ED]  = phi;
            nm = fmaf(disc, nm, gkv);
            den[i] = phi * nm;
        }
        if (tid < 16) {
#pragma unroll
            for (int i = 0; i < 2; i++)
                s_gv[i][tid] = rv[i] * sigmoidf_(rb[i]);
        }

        // interleaved 2-payload shfl den reduction
#pragma unroll
        for (int o = 16; o; o >>= 1) {
            den[0] += __shfl_xor_sync(0xFFFFFFFFu, den[0], o);
            den[1] += __shfl_xor_sync(0xFFFFFFFFu, den[1], o);
        }
        if ((tid & 31) == 0) {
            s_denred[par][0][fg] = den[0];
            s_denred[par][1][fg] = den[1];
        }

        // ---- prefetch chunk c+1 (overlaps barrier + phase B) ----
        if (c < 31) {
#pragma unroll
            for (int i = 0; i < 2; i++) {
                const int tt = (c + 1) * 2 + i;
                const float* Pn = g_proj + (size_t)(tt * B_ + b) * NPROJ_PAD;
                rq[i]  = Pn[hcol + dd];
                rk[i]  = Pn[512 + hcol + dd];
                rg[i]  = Pn[2048 + hcol + dd];
                rp1[i] = Pn[2560 + pofs];
                rp2[i] = Pn[2592 + pofs];
                rp3[i] = Pn[2624 + pofs];
                rtm[i] = term[tt * B_ + b];
                if (tid < 16) {
                    rv[i] = Pn[1024 + hcol + ds * 16 + tid];
                    rb[i] = Pn[1536 + hcol + ds * 16 + tid];
                }
            }
        }

        __syncthreads();

        // ---- phase B: 2 sequential packed kv updates ----
        const int rbase = fg * 32 + jh * 16;
#pragma unroll
        for (int i = 0; i < 2; i++) {
            const unsigned long long gvd2 = pk2(s_gv[i][dloc], s_gv[i][dloc]);
            const ulonglong2* dsc2 = (const ulonglong2*)&s_disc[i][rbase];
            const ulonglong2* gks2 = (const ulonglong2*)&s_gk[i][rbase];
            const ulonglong2* phs2 = (const ulonglong2*)&s_phi[i][rbase];
            unsigned long long np01 = 0ULL, np23 = 0ULL;
#pragma unroll
            for (int jq = 0; jq < 4; jq++) {
                const ulonglong2 D = dsc2[jq];
                const ulonglong2 G = gks2[jq];
                const ulonglong2 Ph = phs2[jq];
                kv2[2*jq]     = fma2_(D.x, kv2[2*jq],     mul2_(gvd2, G.x));
                kv2[2*jq + 1] = fma2_(D.y, kv2[2*jq + 1], mul2_(gvd2, G.y));
                np01 = fma2_(kv2[2*jq],     Ph.x, np01);
                np23 = fma2_(kv2[2*jq + 1], Ph.y, np23);
            }
            float a0, a1, a2, a3;
            unpk2(a0, a1, np01);
            unpk2(a2, a3, np23);
            float np = (a0 + a1) + (a2 + a3);
            // combine the two row-halves (jh) within the warp
            np += __shfl_xor_sync(0xFFFFFFFFu, np, 16);
            if (jh == 0) s_numred[i][fg][dloc] = np;
        }
        __syncthreads();

        // ---- phase C: finalize 2 steps (tid < 32) ----
        if (tid < 32) {
            const int tt = tid >> 4;        // step within chunk
            const int l  = tid & 15;
            float num = 0.f;
#pragma unroll
            for (int g = 0; g < 8; g++) num += s_numred[tt][g][l];
            float dden = 0.f;
#pragma unroll
            for (int g = 0; g < 8; g++) dden += s_denred[par][tt][g];
            const int row = (c * 2 + tt) * B_ + b;
            g_attn[(size_t)row * (H_*DH_) + hcol + ds * 16 + l]
                = num / (dden + 1e-6f);
        }
        // phase C reads are protected by the next chunk's first barrier;
        // s_denred is parity-buffered against next chunk's phase-A writes.
    }

    // Write final states
    float* kvo = kv_out + (size_t)bh * FD_ * DH_;
    {
        const int rbase = fg * 32 + jh * 16;
#pragma unroll
        for (int p = 0; p < 8; p++) {
            float lo, hi;
            unpk2(lo, hi, kv2[p]);
            kvo[(rbase + 2*p    ) * DH_ + d] = lo;
            kvo[(rbase + 2*p + 1) * DH_ + d] = hi;
        }
    }
    if (ds == 0) nm_out[bh * FD_ + ED] = nm;
}

// ---------------------------------------------------------------------------
// Launch
// ---------------------------------------------------------------------------
extern "C" void kernel_launch(void* const* d_in, const int* in_sizes, int n_in,
                              void* d_out, int out_size)
{
    const float* X    = (const float*)d_in[0];
    const int*   term = (const int*)d_in[1];
    const float* kvp  = (const float*)d_in[2];
    const float* nmp  = (const float*)d_in[3];
    const float* Wq   = (const float*)d_in[4];
    const float* Wk   = (const float*)d_in[5];
    const float* Wv   = (const float*)d_in[6];
    const float* Wb   = (const float*)d_in[7];
    const float* Wg   = (const float*)d_in[8];
    const float* Wp1  = (const float*)d_in[9];
    const float* Wp2  = (const float*)d_in[10];
    const float* Wp3  = (const float*)d_in[11];
    const float* Wo   = (const float*)d_in[12];
    const float* bo   = (const float*)d_in[13];
    float* out = (float*)d_out;

    dim3 gp(NPROJ_PAD / BN, MROWS / BM);       // 42 x 16 = 672 blocks
    proj_gemm<<<gp, 256>>>(X, Wq, Wk, Wv, Wb, Wg, Wp1, Wp2, Wp3);

    scan_kernel<<<B_ * H_ * 4, 256>>>(term, kvp, nmp,
                                      out + OUT_OFF_KV, out + OUT_OFF_NM);

    dim3 go(DIM_ / BN, MROWS / BM);            // 8 x 16 = 128 blocks
    out_gemm<<<go, 256>>>(Wo, bo, out);
}

// round 16
// speedup vs baseline: 1.1604x; 1.1604x over previous
#include <cuda_runtime.h>
#include <cuda_bf16.h>
#include <cstdint>

// Problem constants
#define T_ 64
#define B_ 16
#define DIM_ 512
#define H_ 8
#define DH_ 64
#define ETA_ 4
#define FD_ 256           // ETA_*DH_
#define NPROJ 2656        // 5*512 + 3*32
#define NPROJ_PAD 2688
#define MROWS 1024        // T_*B_

// Output layout: output[T,B,DIM], kv_last[B,H,FD,Dh], nm_last[B,H,FD]
#define OUT_OFF_KV  (T_*B_*DIM_)
#define OUT_OFF_NM  (OUT_OFF_KV + B_*H_*FD_*DH_)

// Scratch (device globals — no allocation allowed)
__device__ float g_proj[MROWS * NPROJ_PAD];
__device__ float g_attn[MROWS * (H_*DH_)];

// ---------------------------------------------------------------------------
// f32x2 packed helpers
// ---------------------------------------------------------------------------
__device__ __forceinline__ unsigned long long pk2(float lo, float hi) {
    unsigned long long r;
    asm("mov.b64 %0, {%1, %2};" : "=l"(r) : "f"(lo), "f"(hi));
    return r;
}
__device__ __forceinline__ void unpk2(float& lo, float& hi, unsigned long long v) {
    asm("mov.b64 {%0, %1}, %2;" : "=f"(lo), "=f"(hi) : "l"(v));
}
__device__ __forceinline__ unsigned long long fma2_(unsigned long long a,
                                                    unsigned long long b,
                                                    unsigned long long c) {
    unsigned long long d;
    asm("fma.rn.f32x2 %0, %1, %2, %3;" : "=l"(d) : "l"(a), "l"(b), "l"(c));
    return d;
}
__device__ __forceinline__ unsigned long long mul2_(unsigned long long a,
                                                    unsigned long long b) {
    unsigned long long d;
    asm("mul.rn.f32x2 %0, %1, %2;" : "=l"(d) : "l"(a), "l"(b));
    return d;
}

__device__ __forceinline__ float sigmoidf_(float x) {
    return 1.f / (1.f + __expf(-x));
}

// ---------------------------------------------------------------------------
// GEMM 1: projections — R3/R9 64x64x16 tile, 4x4 micro, 256 thr,
// with DOUBLE-BUFFERED smem (one barrier per k-tile; loads overlap compute).
// ---------------------------------------------------------------------------
#define BM 64
#define BN 64
#define BK 16

__global__ __launch_bounds__(256)
void proj_gemm(const float* __restrict__ X,
               const float* __restrict__ Wq, const float* __restrict__ Wk,
               const float* __restrict__ Wv, const float* __restrict__ Wb,
               const float* __restrict__ Wg, const float* __restrict__ Wp1,
               const float* __restrict__ Wp2, const float* __restrict__ Wp3)
{
    __shared__ float Xs[2][BK][BM + 4];
    __shared__ float Ws[2][BK][BN + 4];

    const int tid = threadIdx.x;
    const int m0 = blockIdx.y * BM;
    const int n0 = blockIdx.x * BN;

    const int lr = tid >> 2;          // 0..63 : row within tile
    const int lc = (tid & 3) * 4;     // 0,4,8,12 : k offset
    const int tx = tid & 15;          // n micro
    const int ty = tid >> 4;          // m micro

    const int n = n0 + lr;
    const float* wrow = nullptr;
    if (n < 2560) {
        const int wi = n >> 9;
        const int nl = n & 511;
        const float* wb = (wi == 0) ? Wq : (wi == 1) ? Wk : (wi == 2) ? Wv
                         : (wi == 3) ? Wb : Wg;
        wrow = wb + nl * DIM_;
    } else if (n < NPROJ) {
        const int nn = n - 2560;
        const int wi = nn >> 5;
        const int nl = nn & 31;
        const float* wb = (wi == 0) ? Wp1 : (wi == 1) ? Wp2 : Wp3;
        wrow = wb + nl * DIM_;
    }
    const float* xrow = X + (size_t)(m0 + lr) * DIM_;

    float acc[4][4];
#pragma unroll
    for (int i = 0; i < 4; i++)
#pragma unroll
        for (int j = 0; j < 4; j++) acc[i][j] = 0.f;

    // prologue: stage k-tile 0 into buffer 0
    {
        float4 xv = *(const float4*)(xrow + lc);
        float4 wv = make_float4(0.f, 0.f, 0.f, 0.f);
        if (wrow) wv = *(const float4*)(wrow + lc);
        Xs[0][lc + 0][lr] = xv.x; Xs[0][lc + 1][lr] = xv.y;
        Xs[0][lc + 2][lr] = xv.z; Xs[0][lc + 3][lr] = xv.w;
        Ws[0][lc + 0][lr] = wv.x; Ws[0][lc + 1][lr] = wv.y;
        Ws[0][lc + 2][lr] = wv.z; Ws[0][lc + 3][lr] = wv.w;
    }
    __syncthreads();

    const int NKT = DIM_ / BK;   // 32
    for (int kt = 0; kt < NKT; kt++) {
        const int buf = kt & 1;

        // issue next tile's global loads before compute (latency overlap)
        float4 nxv, nwv;
        if (kt < NKT - 1) {
            const int ko = (kt + 1) * BK + lc;
            nxv = *(const float4*)(xrow + ko);
            nwv = make_float4(0.f, 0.f, 0.f, 0.f);
            if (wrow) nwv = *(const float4*)(wrow + ko);
        }

#pragma unroll
        for (int kk = 0; kk < BK; kk++) {
            float4 a = *(const float4*)&Xs[buf][kk][ty * 4];
            float4 bq = *(const float4*)&Ws[buf][kk][tx * 4];
            float av[4] = {a.x, a.y, a.z, a.w};
            float bv[4] = {bq.x, bq.y, bq.z, bq.w};
#pragma unroll
            for (int i = 0; i < 4; i++)
#pragma unroll
                for (int j = 0; j < 4; j++) acc[i][j] += av[i] * bv[j];
        }

        if (kt < NKT - 1) {
            const int nb = buf ^ 1;
            Xs[nb][lc + 0][lr] = nxv.x; Xs[nb][lc + 1][lr] = nxv.y;
            Xs[nb][lc + 2][lr] = nxv.z; Xs[nb][lc + 3][lr] = nxv.w;
            Ws[nb][lc + 0][lr] = nwv.x; Ws[nb][lc + 1][lr] = nwv.y;
            Ws[nb][lc + 2][lr] = nwv.z; Ws[nb][lc + 3][lr] = nwv.w;
            __syncthreads();
        }
    }

#pragma unroll
    for (int i = 0; i < 4; i++) {
        const int m = m0 + ty * 4 + i;
#pragma unroll
        for (int j = 0; j < 4; j++) {
            g_proj[(size_t)m * NPROJ_PAD + n0 + tx * 4 + j] = acc[i][j];
        }
    }
}

// ---------------------------------------------------------------------------
// GEMM 2: direct output GEMM with fused bias (R9 measured).
// ---------------------------------------------------------------------------
__global__ __launch_bounds__(256)
void out_gemm(const float* __restrict__ Wo, const float* __restrict__ bo,
              float* __restrict__ out)
{
    __shared__ float Xs[BK][BM + 4];
    __shared__ float Ws[BK][BN + 4];

    const int tid = threadIdx.x;
    const int m0 = blockIdx.y * BM;
    const int n0 = blockIdx.x * BN;

    const int lr = tid >> 2;
    const int lc = (tid & 3) * 4;
    const int tx = tid & 15;
    const int ty = tid >> 4;

    const float* xrow = g_attn + (size_t)(m0 + lr) * DIM_;
    const float* wrow = Wo + (size_t)(n0 + lr) * DIM_;

    float acc[4][4];
#pragma unroll
    for (int i = 0; i < 4; i++)
#pragma unroll
        for (int j = 0; j < 4; j++) acc[i][j] = 0.f;

    for (int k0 = 0; k0 < DIM_; k0 += BK) {
        float4 xv = *(const float4*)(xrow + k0 + lc);
        float4 wv = *(const float4*)(wrow + k0 + lc);
        Xs[lc + 0][lr] = xv.x; Xs[lc + 1][lr] = xv.y;
        Xs[lc + 2][lr] = xv.z; Xs[lc + 3][lr] = xv.w;
        Ws[lc + 0][lr] = wv.x; Ws[lc + 1][lr] = wv.y;
        Ws[lc + 2][lr] = wv.z; Ws[lc + 3][lr] = wv.w;
        __syncthreads();
#pragma unroll
        for (int kk = 0; kk < BK; kk++) {
            float4 a = *(const float4*)&Xs[kk][ty * 4];
            float4 bq = *(const float4*)&Ws[kk][tx * 4];
            float av[4] = {a.x, a.y, a.z, a.w};
            float bv[4] = {bq.x, bq.y, bq.z, bq.w};
#pragma unroll
            for (int i = 0; i < 4; i++)
#pragma unroll
                for (int j = 0; j < 4; j++)
                    acc[i][j] = fmaf(av[i], bv[j], acc[i][j]);
        }
        __syncthreads();
    }

#pragma unroll
    for (int i = 0; i < 4; i++) {
        const int m = m0 + ty * 4 + i;
#pragma unroll
        for (int j = 0; j < 4; j++) {
            const int nn = n0 + tx * 4 + j;
            out[(size_t)m * DIM_ + nn] = acc[i][j] + bo[nn];
        }
    }
}

// ---------------------------------------------------------------------------
// Scan kernel (R9 measured): 2 blocks per (b,h) (d-split), CHUNK-2.
// ---------------------------------------------------------------------------
__global__ __launch_bounds__(256)
void scan_kernel(const int* __restrict__ term,
                 const float* __restrict__ kv_prev,
                 const float* __restrict__ nm_prev,
                 float* __restrict__ kv_out,
                 float* __restrict__ nm_out)
{
    const int blk = blockIdx.x;      // 0..255
    const int bh  = blk >> 1;
    const int ds  = blk & 1;
    const int b   = bh >> 3;
    const int h   = bh & 7;
    const int tid = threadIdx.x;
    const int fg  = tid >> 5;        // FD group (32 rows)
    const int dl  = tid & 31;
    const int d   = ds * 32 + dl;
    const int ED  = tid;
    const int e   = ED >> 6;
    const int dd  = ED & 63;

    __shared__ float s_disc[2][FD_];
    __shared__ float s_gk[2][FD_];
    __shared__ float s_phi[2][FD_];
    __shared__ float s_gv[2][32];
    __shared__ float s_numred[2][8][32];
    __shared__ float s_denred[2][2][8];   // [parity][step][fg]

    unsigned long long kv2[16];
    {
        const float* kvp = kv_prev + (size_t)bh * FD_ * DH_;
#pragma unroll
        for (int p = 0; p < 16; p++) {
            const float lo = kvp[(fg * 32 + 2*p    ) * DH_ + d];
            const float hi = kvp[(fg * 32 + 2*p + 1) * DH_ + d];
            kv2[p] = pk2(lo, hi);
        }
    }
    float nm = nm_prev[bh * FD_ + ED];

    const int hcol = h * DH_;
    const int pofs = h * ETA_ + e;

    float rq[2], rk[2], rg[2], rp1[2], rp2[2], rp3[2], rv[2], rb[2];
    int rtm[2];

#pragma unroll
    for (int i = 0; i < 2; i++) {
        const float* P = g_proj + (size_t)(i * B_ + b) * NPROJ_PAD;
        rq[i]  = P[hcol + dd];
        rk[i]  = P[512 + hcol + dd];
        rg[i]  = P[2048 + hcol + dd];
        rp1[i] = P[2560 + pofs];
        rp2[i] = P[2592 + pofs];
        rp3[i] = P[2624 + pofs];
        rtm[i] = term[i * B_ + b];
        if (tid < 32) {
            rv[i] = P[1024 + hcol + ds * 32 + tid];
            rb[i] = P[1536 + hcol + ds * 32 + tid];
        }
    }

    for (int c = 0; c < 32; c++) {
        const int par = c & 1;

        float den[2];
#pragma unroll
        for (int i = 0; i < 2; i++) {
            const float sgamma = sigmoidf_(rg[i]);
            const float gf   = sigmoidf_(rp3[i]) * sgamma;
            const float mask = rtm[i] ? 0.f : 1.f;
            const float disc = (1.f - gf) * mask;
            const float gkv  = fmaxf(rp1[i], 0.f) * rk[i] * gf;
            const float phi  = fmaxf(rp2[i], 0.f) * rq[i];
            s_disc[i][ED] = disc;
            s_gk[i][ED]   = gkv;
            s_phi[i][ED]  = phi;
            nm = fmaf(disc, nm, gkv);
            den[i] = phi * nm;
        }
        if (tid < 32) {
#pragma unroll
            for (int i = 0; i < 2; i++)
                s_gv[i][tid] = rv[i] * sigmoidf_(rb[i]);
        }

#pragma unroll
        for (int o = 16; o; o >>= 1) {
            den[0] += __shfl_xor_sync(0xFFFFFFFFu, den[0], o);
            den[1] += __shfl_xor_sync(0xFFFFFFFFu, den[1], o);
        }
        if (dl == 0) {
            s_denred[par][0][fg] = den[0];
            s_denred[par][1][fg] = den[1];
        }

        if (c < 31) {
#pragma unroll
            for (int i = 0; i < 2; i++) {
                const int tt = (c + 1) * 2 + i;
                const float* Pn = g_proj + (size_t)(tt * B_ + b) * NPROJ_PAD;
                rq[i]  = Pn[hcol + dd];
                rk[i]  = Pn[512 + hcol + dd];
                rg[i]  = Pn[2048 + hcol + dd];
                rp1[i] = Pn[2560 + pofs];
                rp2[i] = Pn[2592 + pofs];
                rp3[i] = Pn[2624 + pofs];
                rtm[i] = term[tt * B_ + b];
                if (tid < 32) {
                    rv[i] = Pn[1024 + hcol + ds * 32 + tid];
                    rb[i] = Pn[1536 + hcol + ds * 32 + tid];
                }
            }
        }

        __syncthreads();

#pragma unroll
        for (int i = 0; i < 2; i++) {
            const unsigned long long gvd2 = pk2(s_gv[i][dl], s_gv[i][dl]);
            const ulonglong2* dsc2 = (const ulonglong2*)&s_disc[i][fg * 32];
            const ulonglong2* gks2 = (const ulonglong2*)&s_gk[i][fg * 32];
            const ulonglong2* phs2 = (const ulonglong2*)&s_phi[i][fg * 32];
            unsigned long long np01 = 0ULL, np23 = 0ULL;
#pragma unroll
            for (int jq = 0; jq < 8; jq++) {
                const ulonglong2 D = dsc2[jq];
                const ulonglong2 G = gks2[jq];
                const ulonglong2 Ph = phs2[jq];
                kv2[2*jq]     = fma2_(D.x, kv2[2*jq],     mul2_(gvd2, G.x));
                kv2[2*jq + 1] = fma2_(D.y, kv2[2*jq + 1], mul2_(gvd2, G.y));
                np01 = fma2_(kv2[2*jq],     Ph.x, np01);
                np23 = fma2_(kv2[2*jq + 1], Ph.y, np23);
            }
            float a0, a1, a2, a3;
            unpk2(a0, a1, np01);
            unpk2(a2, a3, np23);
            s_numred[i][fg][dl] = (a0 + a1) + (a2 + a3);
        }
        __syncthreads();

        if (tid < 64) {
            const int tt = tid >> 5;
            const int l  = tid & 31;
            float num = 0.f;
#pragma unroll
            for (int g = 0; g < 8; g++) num += s_numred[tt][g][l];
            float dden = 0.f;
#pragma unroll
            for (int g = 0; g < 8; g++) dden += s_denred[par][tt][g];
            const int row = (c * 2 + tt) * B_ + b;
            g_attn[(size_t)row * (H_*DH_) + hcol + ds * 32 + l]
                = num / (dden + 1e-6f);
        }
    }

    float* kvo = kv_out + (size_t)bh * FD_ * DH_;
#pragma unroll
    for (int p = 0; p < 16; p++) {
        float lo, hi;
        unpk2(lo, hi, kv2[p]);
        kvo[(fg * 32 + 2*p    ) * DH_ + d] = lo;
        kvo[(fg * 32 + 2*p + 1) * DH_ + d] = hi;
    }
    if (ds == 0) nm_out[bh * FD_ + ED] = nm;
}

// ---------------------------------------------------------------------------
// Launch
// ---------------------------------------------------------------------------
extern "C" void kernel_launch(void* const* d_in, const int* in_sizes, int n_in,
                              void* d_out, int out_size)
{
    const float* X    = (const float*)d_in[0];
    const int*   term = (const int*)d_in[1];
    const float* kvp  = (const float*)d_in[2];
    const float* nmp  = (const float*)d_in[3];
    const float* Wq   = (const float*)d_in[4];
    const float* Wk   = (const float*)d_in[5];
    const float* Wv   = (const float*)d_in[6];
    const float* Wb   = (const float*)d_in[7];
    const float* Wg   = (const float*)d_in[8];
    const float* Wp1  = (const float*)d_in[9];
    const float* Wp2  = (const float*)d_in[10];
    const float* Wp3  = (const float*)d_in[11];
    const float* Wo   = (const float*)d_in[12];
    const float* bo   = (const float*)d_in[13];
    float* out = (float*)d_out;

    dim3 gp(NPROJ_PAD / BN, MROWS / BM);       // 42 x 16 = 672 blocks
    proj_gemm<<<gp, 256>>>(X, Wq, Wk, Wv, Wb, Wg, Wp1, Wp2, Wp3);

    scan_kernel<<<B_ * H_ * 2, 256>>>(term, kvp, nmp,
                                      out + OUT_OFF_KV, out + OUT_OFF_NM);

    dim3 go(DIM_ / BN, MROWS / BM);            // 8 x 16 = 128 blocks
    out_gemm<<<go, 256>>>(Wo, bo, out);
}